// round 14
// baseline (speedup 1.0000x reference)
#include <cuda_runtime.h>
#include <math.h>
#include <stdint.h>

// ---------------------------------------------------------------------------
// Problem constants
// ---------------------------------------------------------------------------
#define Bz   2
#define Cc   256
#define NH   8
#define HD   32
#define NN   4096
#define CPG  32
#define EPSV 1e-5f
#define LOG2E 1.4426950408889634f

// K tile block: [kt:4][q:4][136]  (128 used, pad->8 mod 32 banks)
#define KT_ROW   136
#define KT_BLK   (4 * 4 * KT_ROW)      // 2176 uint = 8704 B
// V tile block: [grp:8][qi:4][72] (64 used, pad->8 mod 32 banks)
#define VT_ROW   72
#define VT_BLK   (8 * 4 * VT_ROW)      // 2304 uint = 9216 B
#define KT_BYTES (KT_BLK * 4)          // 8704
#define VT_BYTES (VT_BLK * 4)          // 9216
#define TILE_BYTES (KT_BYTES + VT_BYTES)  // 17920

// ---------------------------------------------------------------------------
// Scratch (device globals — no allocation allowed)
// ---------------------------------------------------------------------------
__device__ float g_psum[128];
__device__ float g_psq[128];
__device__ float g_mean[16];
__device__ float g_rstd[16];
// Q in mma-fragment layout: [bh][chunk:256][kt:4][lane:32][j:4], tf32, pre-scaled
__device__ uint32_t g_q2[16 * 256 * 4 * 32 * 4];
// K in attention smem layout per 64-key tile
__device__ uint32_t g_k2[16 * 64 * KT_BLK];
// V in attention smem layout per 64-key tile
__device__ uint32_t g_v2[16 * 64 * VT_BLK];
__device__ float g_o[Bz * Cc * NN];        // [b][c][n]

// ---------------------------------------------------------------------------
// Helpers
// ---------------------------------------------------------------------------
__device__ __forceinline__ uint32_t f2tf(float x) {
    uint32_t r;
    asm("cvt.rna.tf32.f32 %0, %1;" : "=r"(r) : "f"(x));
    return r;
}
__device__ __forceinline__ float ex2f(float x) {
    float r;
    asm("ex2.approx.f32 %0, %1;" : "=f"(r) : "f"(x));
    return r;
}
__device__ __forceinline__ void mma_tf32(float d[4], const uint32_t a[4],
                                         const uint32_t b[2], const float c[4]) {
    asm volatile(
        "mma.sync.aligned.m16n8k8.row.col.f32.tf32.tf32.f32 "
        "{%0,%1,%2,%3}, {%4,%5,%6,%7}, {%8,%9}, {%10,%11,%12,%13};"
        : "=f"(d[0]), "=f"(d[1]), "=f"(d[2]), "=f"(d[3])
        : "r"(a[0]), "r"(a[1]), "r"(a[2]), "r"(a[3]),
          "r"(b[0]), "r"(b[1]),
          "f"(c[0]), "f"(c[1]), "f"(c[2]), "f"(c[3]));
}
#define CP16(dst_u32, src_ptr) \
    asm volatile("cp.async.ca.shared.global [%0], [%1], 16;" \
                 :: "r"(dst_u32), "l"(src_ptr))
#define CP_COMMIT() asm volatile("cp.async.commit_group;")

// ---------------------------------------------------------------------------
// Kernel 1: GroupNorm stats
// ---------------------------------------------------------------------------
__global__ __launch_bounds__(256) void gn_stats_partial(const float* __restrict__ x) {
    int blk  = blockIdx.x;
    int bg   = blk >> 3;
    int part = blk & 7;
    const float4* p4 = (const float4*)(x + (size_t)bg * CPG * NN + (size_t)part * (CPG * NN / 8));
    const int n4 = (CPG * NN / 8) / 4;
    float s = 0.f, sq = 0.f;
    for (int i = threadIdx.x; i < n4; i += 256) {
        float4 v = p4[i];
        s  += v.x + v.y + v.z + v.w;
        sq += v.x * v.x + v.y * v.y + v.z * v.z + v.w * v.w;
    }
    __shared__ float ss[8], ssq[8];
    for (int o = 16; o; o >>= 1) {
        s  += __shfl_xor_sync(0xffffffffu, s,  o);
        sq += __shfl_xor_sync(0xffffffffu, sq, o);
    }
    if ((threadIdx.x & 31) == 0) { ss[threadIdx.x >> 5] = s; ssq[threadIdx.x >> 5] = sq; }
    __syncthreads();
    if (threadIdx.x == 0) {
        float S = 0.f, SQ = 0.f;
        for (int i = 0; i < 8; i++) { S += ss[i]; SQ += ssq[i]; }
        g_psum[blk] = S;
        g_psq[blk]  = SQ;
    }
}

__global__ void gn_stats_final() {
    int bg = threadIdx.x;
    if (bg >= 16) return;
    float S = 0.f, SQ = 0.f;
    for (int i = 0; i < 8; i++) { S += g_psum[bg * 8 + i]; SQ += g_psq[bg * 8 + i]; }
    const float inv = 1.0f / (float)(CPG * NN);
    float mean = S * inv;
    float var  = SQ * inv - mean * mean;
    g_mean[bg] = mean;
    g_rstd[bg] = rsqrtf(var + EPSV);
}

// ---------------------------------------------------------------------------
// Kernel 2: QKV GEMM (tf32), GN fused on load, pixel permutation folded into
// B staging (R13). NEW: register software-pipeline — next k-iter's A and B
// gmem loads issue right after the staging sync, completing under this
// iteration's mma burst. Staging is pure regs->STS.
// ---------------------------------------------------------------------------
__global__ __launch_bounds__(256, 2) void qkv_tc_kernel(
    const float* __restrict__ x, const float* __restrict__ gnw,
    const float* __restrict__ gnb, const float* __restrict__ W,
    const float* __restrict__ bias) {
    __shared__ __align__(16) uint32_t Ap[4][4][272];
    __shared__ __align__(16) uint32_t Bp[4][4][272];
    const int b  = blockIdx.z;
    const int o0 = blockIdx.y * 128;
    const int n0 = blockIdx.x * 128;
    const int tid = threadIdx.x, wid = tid >> 5, lane = tid & 31;
    const int r = lane >> 2, q = lane & 3;
    const int wr = wid >> 2, wc = wid & 3;
    const int which = o0 >> 8;              // 0=q 1=k 2=v (uniform per block)
    const float sc2 = 0.17677669529663687f * LOG2E;

    // staging index precomputes (loop-invariant)
    const int a_row = tid >> 3, a_c4 = tid & 7;          // A: rows a_row, a_row+? (it)
    const int b_cch = tid >> 5, b_nq = (tid & 31) << 2;  // B: per-it adds

    float acc[4][4][4];
#pragma unroll
    for (int mt = 0; mt < 4; mt++)
#pragma unroll
        for (int nt = 0; nt < 4; nt++)
#pragma unroll
            for (int j = 0; j < 4; j++) acc[mt][nt][j] = 0.f;

    // ---- prefetch k0 = 0 ----
    float4 wv4[4], xv4[4];
#pragma unroll
    for (int it = 0; it < 4; it++) {
        int row = a_row + 32 * it;
        wv4[it] = *(const float4*)&W[(size_t)(o0 + row) * Cc + a_c4 * 4];
    }
#pragma unroll
    for (int it = 0; it < 4; it++) {
        int cch = b_cch + 8 * it;
        xv4[it] = *(const float4*)&x[((size_t)b * Cc + cch) * NN + n0 + b_nq];
    }

    for (int k0 = 0; k0 < Cc; k0 += 32) {
        __syncthreads();
        // stage A from regs
#pragma unroll
        for (int it = 0; it < 4; it++) {
            int row = a_row + 32 * it;
            float wv[4] = {wv4[it].x, wv4[it].y, wv4[it].z, wv4[it].w};
#pragma unroll
            for (int j = 0; j < 4; j++) {
                int k = a_c4 * 4 + j, i = k & 7;
                Ap[k >> 3][i & 3][2 * row + (i >> 2)] = f2tf(wv[j]);
            }
        }
        // stage B from regs: GN + pixel permutation into column order
        const float mu  = g_mean[b * 8 + (k0 >> 5)];
        const float rsd = g_rstd[b * 8 + (k0 >> 5)];
#pragma unroll
        for (int it = 0; it < 4; it++) {
            int cch = b_cch + 8 * it;
            int ch  = k0 + cch;
            float gw = gnw[ch], gb = gnb[ch];
            int pl = cch >> 3, ii = cch & 7;
            int iq = ii & 3, ih = ii >> 2;
            float vv[4] = {xv4[it].x, xv4[it].y, xv4[it].z, xv4[it].w};
#pragma unroll
            for (int j = 0; j < 4; j++) {
                int n = b_nq + j;
                int cpos;
                if (which == 0) {
                    cpos = (n & ~15) | ((n & 7) << 1) | ((n >> 3) & 1);
                } else {
                    int kk = n & 7;
                    cpos = (n & ~7) + ((kk < 4) ? 2 * kk : 2 * kk - 7);
                }
                float gv = (vv[j] - mu) * rsd * gw + gb;
                Bp[pl][iq][2 * cpos + ih] = f2tf(gv);
            }
        }
        __syncthreads();

        // prefetch next k-iter (hidden under the mma burst below)
        if (k0 + 32 < Cc) {
#pragma unroll
            for (int it = 0; it < 4; it++) {
                int row = a_row + 32 * it;
                wv4[it] = *(const float4*)&W[(size_t)(o0 + row) * Cc + (k0 + 32) + a_c4 * 4];
            }
#pragma unroll
            for (int it = 0; it < 4; it++) {
                int cch = b_cch + 8 * it;
                xv4[it] = *(const float4*)&x[((size_t)b * Cc + (k0 + 32) + cch) * NN + n0 + b_nq];
            }
        }

#pragma unroll
        for (int kt = 0; kt < 4; kt++) {
            uint32_t af[4][4];
#pragma unroll
            for (int mt = 0; mt < 4; mt++) {
                int m = wr * 64 + mt * 16;
                uint2 lo = *(const uint2*)&Ap[kt][q][2 * (m + r)];
                uint2 hi = *(const uint2*)&Ap[kt][q][2 * (m + 8 + r)];
                af[mt][0] = lo.x; af[mt][1] = hi.x; af[mt][2] = lo.y; af[mt][3] = hi.y;
            }
            uint2 bfv[4];
#pragma unroll
            for (int nt = 0; nt < 4; nt++)
                bfv[nt] = *(const uint2*)&Bp[kt][q][2 * (wc * 32 + nt * 8 + r)];
#pragma unroll
            for (int mt = 0; mt < 4; mt++)
#pragma unroll
                for (int nt = 0; nt < 4; nt++) {
                    uint32_t bb[2] = {bfv[nt].x, bfv[nt].y};
                    mma_tf32(acc[mt][nt], af[mt], bb, acc[mt][nt]);
                }
        }
    }

    // ---- epilogue: affine addresses (permutation already in column order) --
    const size_t bb0 = (size_t)b * NH;
    if (which == 0) {
#pragma unroll
        for (int mt = 0; mt < 4; mt++)
#pragma unroll
            for (int hf_i = 0; hf_i < 2; hf_i++) {
                int row = o0 + wr * 64 + mt * 16 + r + 8 * hf_i;
                float bi = bias[row];
                int h = (row >> 5) & 7, d = row & 31;
                int kt2 = d >> 3, qq2 = d & 3, hf = (d >> 2) & 1;
                uint32_t* qb = g_q2 + ((bb0 + h) * 256 + (n0 >> 4)) * 512
                               + kt2 * 128 + qq2 * 4 + 2 * hf;
#pragma unroll
                for (int nt = 0; nt < 4; nt++) {
                    int c = wc * 32 + nt * 8 + 2 * q;
                    uint2 v;
                    v.x = f2tf((acc[mt][nt][hf_i * 2 + 0] + bi) * sc2);
                    v.y = f2tf((acc[mt][nt][hf_i * 2 + 1] + bi) * sc2);
                    *(uint2*)&qb[(c >> 4) * 512 + ((c >> 1) & 7) * 16] = v;
                }
            }
    } else if (which == 1) {
#pragma unroll
        for (int mt = 0; mt < 4; mt++)
#pragma unroll
            for (int hf_i = 0; hf_i < 2; hf_i++) {
                int row = o0 + wr * 64 + mt * 16 + r + 8 * hf_i;
                float bi = bias[row];
                int h = (row >> 5) & 7, d = row & 31;
                int plane = (d >> 3) * 4 + (d & 3), hf = (d >> 2) & 1;
                uint32_t* kb = g_k2 + (bb0 + h) * 64 * KT_BLK
                               + (size_t)(n0 >> 6) * KT_BLK + plane * KT_ROW + hf;
#pragma unroll
                for (int nt = 0; nt < 4; nt++)
#pragma unroll
                    for (int jj = 0; jj < 2; jj++) {
                        int c = wc * 32 + nt * 8 + 2 * q + jj;
                        kb[(c >> 6) * KT_BLK + 2 * (c & 63)] =
                            f2tf(acc[mt][nt][hf_i * 2 + jj] + bi);
                    }
            }
    } else {
#pragma unroll
        for (int mt = 0; mt < 4; mt++)
#pragma unroll
            for (int hf_i = 0; hf_i < 2; hf_i++) {
                int row = o0 + wr * 64 + mt * 16 + r + 8 * hf_i;
                float bi = bias[row];
                int h = (row >> 5) & 7, d = row & 31;
                uint32_t* vb = g_v2 + (bb0 + h) * 64 * VT_BLK
                               + (size_t)(n0 >> 6) * VT_BLK + 2 * d;
#pragma unroll
                for (int nt = 0; nt < 4; nt++) {
                    int c = wc * 32 + nt * 8 + 2 * q;
                    int plane = ((c & 63) >> 3) * 4 + q;
                    uint2 v;
                    v.x = f2tf(acc[mt][nt][hf_i * 2 + 0] + bi);
                    v.y = f2tf(acc[mt][nt][hf_i * 2 + 1] + bi);
                    *(uint2*)&vb[(c >> 6) * VT_BLK + plane * VT_ROW] = v;
                }
            }
    }
}

// ---------------------------------------------------------------------------
// Kernel 3: flash attention (round-11 best config, unchanged).
// ---------------------------------------------------------------------------
__global__ __launch_bounds__(256, 2) void attn_tc_kernel() {
    __shared__ __align__(16) uint32_t Ks[2][KT_BLK];
    __shared__ __align__(16) uint32_t Vs[2][VT_BLK];

    const int b  = blockIdx.z;
    const int h  = blockIdx.y;
    const int q0 = blockIdx.x * 256;
    const int tid = threadIdx.x, wid = tid >> 5, lane = tid & 31;
    const int r = lane >> 2, q = lane & 3;
    const size_t bh = (size_t)b * NH + h;

    uint32_t qa[2][4][4];
#pragma unroll
    for (int mt = 0; mt < 2; mt++) {
        const int chunk = (q0 >> 4) + wid * 2 + mt;
#pragma unroll
        for (int kt = 0; kt < 4; kt++) {
            uint4 v4 = *(const uint4*)&g_q2[(((bh * 256 + chunk) * 4 + kt) * 32 + lane) * 4];
            qa[mt][kt][0] = v4.x; qa[mt][kt][1] = v4.y;
            qa[mt][kt][2] = v4.z; qa[mt][kt][3] = v4.w;
        }
    }

    float o0a[4][4], o1a[4][4];
#pragma unroll
    for (int i = 0; i < 4; i++)
#pragma unroll
        for (int j = 0; j < 4; j++) { o0a[i][j] = 0.f; o1a[i][j] = 0.f; }
    float lsum[2][2] = {{0.f, 0.f}, {0.f, 0.f}};

    const char* kgm = (const char*)(g_k2 + bh * 64 * KT_BLK);
    const char* vgm = (const char*)(g_v2 + bh * 64 * VT_BLK);
    uint32_t ks_s[2], vs_s[2];
    ks_s[0] = (uint32_t)__cvta_generic_to_shared(&Ks[0][0]);
    ks_s[1] = (uint32_t)__cvta_generic_to_shared(&Ks[1][0]);
    vs_s[0] = (uint32_t)__cvta_generic_to_shared(&Vs[0][0]);
    vs_s[1] = (uint32_t)__cvta_generic_to_shared(&Vs[1][0]);

    {
        for (int off = tid * 16; off < TILE_BYTES; off += 4096) {
            if (off < KT_BYTES) CP16(ks_s[0] + off, kgm + off);
            else                CP16(vs_s[0] + (off - KT_BYTES), vgm + (off - KT_BYTES));
        }
        CP_COMMIT();
    }

#pragma unroll 1
    for (int t = 0; t < NN / 64; t++) {
        const int cur = t & 1;
        const bool more = (t + 1 < NN / 64);
        if (more) {
            const char* ksrc = kgm + (size_t)(t + 1) * KT_BYTES;
            const char* vsrc = vgm + (size_t)(t + 1) * VT_BYTES;
            const int nxt = 1 - cur;
            for (int off = tid * 16; off < TILE_BYTES; off += 4096) {
                if (off < KT_BYTES) CP16(ks_s[nxt] + off, ksrc + off);
                else                CP16(vs_s[nxt] + (off - KT_BYTES), vsrc + (off - KT_BYTES));
            }
            CP_COMMIT();
            asm volatile("cp.async.wait_group 1;");
        } else {
            asm volatile("cp.async.wait_group 0;");
        }
        __syncthreads();

        const uint32_t* Kc = Ks[cur];
        const uint32_t* Vc = Vs[cur];

        float s0[8][4], s1[8][4];
        float rs00 = 0.f, rs01 = 0.f, rs10 = 0.f, rs11 = 0.f;

#pragma unroll
        for (int nt = 0; nt < 8; nt++) {
            uint2 bfk[4];
#pragma unroll
            for (int kt = 0; kt < 4; kt++)
                bfk[kt] = *(const uint2*)&Kc[(kt * 4 + q) * KT_ROW + 2 * (nt * 8 + r)];
#pragma unroll
            for (int j = 0; j < 4; j++) { s0[nt][j] = 0.f; s1[nt][j] = 0.f; }
#pragma unroll
            for (int kt = 0; kt < 4; kt++) {
                uint32_t bb[2] = {bfk[kt].x, bfk[kt].y};
                mma_tf32(s0[nt], qa[0][kt], bb, s0[nt]);
                mma_tf32(s1[nt], qa[1][kt], bb, s1[nt]);
            }
            if (nt > 0) {
                const int p = nt - 1;
                s0[p][0] = ex2f(s0[p][0]); rs00 += s0[p][0];
                s0[p][1] = ex2f(s0[p][1]); rs00 += s0[p][1];
                s0[p][2] = ex2f(s0[p][2]); rs01 += s0[p][2];
                s0[p][3] = ex2f(s0[p][3]); rs01 += s0[p][3];
            }
        }
        s0[7][0] = ex2f(s0[7][0]); rs00 += s0[7][0];
        s0[7][1] = ex2f(s0[7][1]); rs00 += s0[7][1];
        s0[7][2] = ex2f(s0[7][2]); rs01 += s0[7][2];
        s0[7][3] = ex2f(s0[7][3]); rs01 += s0[7][3];

        s1[0][0] = ex2f(s1[0][0]); rs10 += s1[0][0];
        s1[0][1] = ex2f(s1[0][1]); rs10 += s1[0][1];
        s1[0][2] = ex2f(s1[0][2]); rs11 += s1[0][2];
        s1[0][3] = ex2f(s1[0][3]); rs11 += s1[0][3];

#pragma unroll
        for (int grp = 0; grp < 8; grp++) {
            if (grp < 7) {
                const int p = grp + 1;
                s1[p][0] = ex2f(s1[p][0]); rs10 += s1[p][0];
                s1[p][1] = ex2f(s1[p][1]); rs10 += s1[p][1];
                s1[p][2] = ex2f(s1[p][2]); rs11 += s1[p][2];
                s1[p][3] = ex2f(s1[p][3]); rs11 += s1[p][3];
            }
            const uint32_t* vr2 = Vc + (grp * 4 + q) * VT_ROW;
            uint32_t pa0[4], pa1[4];
            pa0[0] = __float_as_uint(s0[grp][0]);
            pa0[1] = __float_as_uint(s0[grp][2]);
            pa0[2] = __float_as_uint(s0[grp][1]);
            pa0[3] = __float_as_uint(s0[grp][3]);
            pa1[0] = __float_as_uint(s1[grp][0]);
            pa1[1] = __float_as_uint(s1[grp][2]);
            pa1[2] = __float_as_uint(s1[grp][1]);
            pa1[3] = __float_as_uint(s1[grp][3]);
#pragma unroll
            for (int nt = 0; nt < 4; nt++) {
                uint2 bf = *(const uint2*)&vr2[2 * (nt * 8 + r)];
                uint32_t bb[2] = {bf.x, bf.y};
                mma_tf32(o0a[nt], pa0, bb, o0a[nt]);
                mma_tf32(o1a[nt], pa1, bb, o1a[nt]);
            }
        }
        lsum[0][0] += rs00; lsum[0][1] += rs01;
        lsum[1][0] += rs10; lsum[1][1] += rs11;
        __syncthreads();
    }

#pragma unroll
    for (int mt = 0; mt < 2; mt++) {
        float rs0 = lsum[mt][0], rs1 = lsum[mt][1];
        rs0 += __shfl_xor_sync(0xffffffffu, rs0, 1);
        rs0 += __shfl_xor_sync(0xffffffffu, rs0, 2);
        rs1 += __shfl_xor_sync(0xffffffffu, rs1, 1);
        rs1 += __shfl_xor_sync(0xffffffffu, rs1, 2);
        float inv0 = 1.0f / rs0, inv1 = 1.0f / rs1;
        const int gr0 = q0 + wid * 32 + mt * 16 + r;
        const int gr1 = gr0 + 8;
        float (*oo)[4] = (mt == 0) ? o0a : o1a;
#pragma unroll
        for (int nt = 0; nt < 4; nt++) {
            int d = nt * 8 + 2 * q;
            float* base = g_o + (bh * HD + d) * NN;
            base[gr0]      = oo[nt][0] * inv0;
            base[NN + gr0] = oo[nt][1] * inv0;
            base[gr1]      = oo[nt][2] * inv1;
            base[NN + gr1] = oo[nt][3] * inv1;
        }
    }
}

// ---------------------------------------------------------------------------
// Kernel 4: output projection GEMM (tf32), register software-pipelined loads.
// ---------------------------------------------------------------------------
__global__ __launch_bounds__(256, 2) void proj_tc_kernel(
    const float* __restrict__ W, const float* __restrict__ bias,
    float* __restrict__ out) {
    __shared__ __align__(16) uint32_t Ap[4][4][272];
    __shared__ __align__(16) uint32_t Bp[4][4][272];
    const int b  = blockIdx.z;
    const int o0 = blockIdx.y * 128;
    const int n0 = blockIdx.x * 128;
    const int tid = threadIdx.x, wid = tid >> 5, lane = tid & 31;
    const int r = lane >> 2, q = lane & 3;
    const int wr = wid >> 2, wc = wid & 3;

    const int a_row = tid >> 3, a_c4 = tid & 7;
    const int b_cch = tid >> 5, b_nq = (tid & 31) << 2;

    float acc[4][4][4];
#pragma unroll
    for (int mt = 0; mt < 4; mt++)
#pragma unroll
        for (int nt = 0; nt < 4; nt++)
#pragma unroll
            for (int j = 0; j < 4; j++) acc[mt][nt][j] = 0.f;

    float4 wv4[4], xv4[4];
#pragma unroll
    for (int it = 0; it < 4; it++) {
        int row = a_row + 32 * it;
        wv4[it] = *(const float4*)&W[(size_t)(o0 + row) * Cc + a_c4 * 4];
    }
#pragma unroll
    for (int it = 0; it < 4; it++) {
        int cch = b_cch + 8 * it;
        xv4[it] = *(const float4*)&g_o[((size_t)b * Cc + cch) * NN + n0 + b_nq];
    }

    for (int k0 = 0; k0 < Cc; k0 += 32) {
        __syncthreads();
#pragma unroll
        for (int it = 0; it < 4; it++) {
            int row = a_row + 32 * it;
            float wv[4] = {wv4[it].x, wv4[it].y, wv4[it].z, wv4[it].w};
#pragma unroll
            for (int j = 0; j < 4; j++) {
                int k = a_c4 * 4 + j, i = k & 7;
                Ap[k >> 3][i & 3][2 * row + (i >> 2)] = f2tf(wv[j]);
            }
        }
#pragma unroll
        for (int it = 0; it < 4; it++) {
            int cch = b_cch + 8 * it;
            int pl = cch >> 3, ii = cch & 7;
            int iq = ii & 3, ih = ii >> 2;
            float vv[4] = {xv4[it].x, xv4[it].y, xv4[it].z, xv4[it].w};
#pragma unroll
            for (int j = 0; j < 4; j++)
                Bp[pl][iq][2 * (b_nq + j) + ih] = f2tf(vv[j]);
        }
        __syncthreads();

        if (k0 + 32 < Cc) {
#pragma unroll
            for (int it = 0; it < 4; it++) {
                int row = a_row + 32 * it;
                wv4[it] = *(const float4*)&W[(size_t)(o0 + row) * Cc + (k0 + 32) + a_c4 * 4];
            }
#pragma unroll
            for (int it = 0; it < 4; it++) {
                int cch = b_cch + 8 * it;
                xv4[it] = *(const float4*)&g_o[((size_t)b * Cc + (k0 + 32) + cch) * NN + n0 + b_nq];
            }
        }

#pragma unroll
        for (int kt = 0; kt < 4; kt++) {
            uint32_t af[4][4];
#pragma unroll
            for (int mt = 0; mt < 4; mt++) {
                int m = wr * 64 + mt * 16;
                uint2 lo = *(const uint2*)&Ap[kt][q][2 * (m + r)];
                uint2 hi = *(const uint2*)&Ap[kt][q][2 * (m + 8 + r)];
                af[mt][0] = lo.x; af[mt][1] = hi.x; af[mt][2] = lo.y; af[mt][3] = hi.y;
            }
            uint2 bfv[4];
#pragma unroll
            for (int nt = 0; nt < 4; nt++)
                bfv[nt] = *(const uint2*)&Bp[kt][q][2 * (wc * 32 + nt * 8 + r)];
#pragma unroll
            for (int mt = 0; mt < 4; mt++)
#pragma unroll
                for (int nt = 0; nt < 4; nt++) {
                    uint32_t bb[2] = {bfv[nt].x, bfv[nt].y};
                    mma_tf32(acc[mt][nt], af[mt], bb, acc[mt][nt]);
                }
        }
    }

#pragma unroll
    for (int mt = 0; mt < 4; mt++) {
        int row0 = o0 + wr * 64 + mt * 16 + r;
        int row1 = row0 + 8;
        float bi0 = bias[row0], bi1 = bias[row1];
        float* p0 = out + ((size_t)b * Cc + row0) * NN;
        float* p1 = out + ((size_t)b * Cc + row1) * NN;
#pragma unroll
        for (int nt = 0; nt < 4; nt++) {
            int n = n0 + wc * 32 + nt * 8 + 2 * q;
            float2 v0 = make_float2(acc[mt][nt][0] + bi0, acc[mt][nt][1] + bi0);
            float2 v1 = make_float2(acc[mt][nt][2] + bi1, acc[mt][nt][3] + bi1);
            *(float2*)&p0[n] = v0;
            *(float2*)&p1[n] = v1;
        }
    }
}

// ---------------------------------------------------------------------------
// Launch
// ---------------------------------------------------------------------------
extern "C" void kernel_launch(void* const* d_in, const int* in_sizes, int n_in,
                              void* d_out, int out_size) {
    const float* x    = (const float*)d_in[0];
    const float* gnw  = (const float*)d_in[1];
    const float* gnb  = (const float*)d_in[2];
    const float* wqkv = (const float*)d_in[3];
    const float* bqkv = (const float*)d_in[4];
    const float* wproj= (const float*)d_in[5];
    const float* bproj= (const float*)d_in[6];
    float* out = (float*)d_out;

    gn_stats_partial<<<128, 256>>>(x);
    gn_stats_final<<<1, 16>>>();

    dim3 gq(NN / 128, (3 * Cc) / 128, Bz);
    qkv_tc_kernel<<<gq, 256>>>(x, gnw, gnb, wqkv, bqkv);

    dim3 ga(NN / 256, NH, Bz);
    attn_tc_kernel<<<ga, 256>>>();

    dim3 gp(NN / 128, Cc / 128, Bz);
    proj_tc_kernel<<<gp, 256>>>(wproj, bproj, out);
}

// round 15
// speedup vs baseline: 1.0099x; 1.0099x over previous
#include <cuda_runtime.h>
#include <math.h>
#include <stdint.h>

// ---------------------------------------------------------------------------
// Problem constants
// ---------------------------------------------------------------------------
#define Bz   2
#define Cc   256
#define NH   8
#define HD   32
#define NN   4096
#define CPG  32
#define EPSV 1e-5f
#define LOG2E 1.4426950408889634f

// K tile block: [kt:4][q:4][136]  (128 used, pad->8 mod 32 banks)
#define KT_ROW   136
#define KT_BLK   (4 * 4 * KT_ROW)      // 2176 uint = 8704 B
// V tile block: [grp:8][qi:4][72] (64 used, pad->8 mod 32 banks)
#define VT_ROW   72
#define VT_BLK   (8 * 4 * VT_ROW)      // 2304 uint = 9216 B
#define KT_BYTES (KT_BLK * 4)          // 8704
#define VT_BYTES (VT_BLK * 4)          // 9216
#define TILE_BYTES (KT_BYTES + VT_BYTES)  // 17920

// ---------------------------------------------------------------------------
// Scratch (device globals — no allocation allowed)
// ---------------------------------------------------------------------------
__device__ float g_psum[128];
__device__ float g_psq[128];
__device__ float g_mean[16];
__device__ float g_rstd[16];
// Q in mma-fragment layout: [bh][chunk:256][kt:4][lane:32][j:4], tf32, pre-scaled
__device__ uint32_t g_q2[16 * 256 * 4 * 32 * 4];
// K in attention smem layout per 64-key tile
__device__ uint32_t g_k2[16 * 64 * KT_BLK];
// V in attention smem layout per 64-key tile
__device__ uint32_t g_v2[16 * 64 * VT_BLK];
__device__ float g_o[Bz * Cc * NN];        // [b][c][n]

// ---------------------------------------------------------------------------
// Helpers
// ---------------------------------------------------------------------------
__device__ __forceinline__ uint32_t f2tf(float x) {
    uint32_t r;
    asm("cvt.rna.tf32.f32 %0, %1;" : "=r"(r) : "f"(x));
    return r;
}
__device__ __forceinline__ float ex2f(float x) {
    float r;
    asm("ex2.approx.f32 %0, %1;" : "=f"(r) : "f"(x));
    return r;
}
__device__ __forceinline__ void mma_tf32(float d[4], const uint32_t a[4],
                                         const uint32_t b[2], const float c[4]) {
    asm volatile(
        "mma.sync.aligned.m16n8k8.row.col.f32.tf32.tf32.f32 "
        "{%0,%1,%2,%3}, {%4,%5,%6,%7}, {%8,%9}, {%10,%11,%12,%13};"
        : "=f"(d[0]), "=f"(d[1]), "=f"(d[2]), "=f"(d[3])
        : "r"(a[0]), "r"(a[1]), "r"(a[2]), "r"(a[3]),
          "r"(b[0]), "r"(b[1]),
          "f"(c[0]), "f"(c[1]), "f"(c[2]), "f"(c[3]));
}
#define CP16(dst_u32, src_ptr) \
    asm volatile("cp.async.ca.shared.global [%0], [%1], 16;" \
                 :: "r"(dst_u32), "l"(src_ptr))
#define CP_COMMIT() asm volatile("cp.async.commit_group;")

// ---------------------------------------------------------------------------
// Kernel 1: GroupNorm stats
// ---------------------------------------------------------------------------
__global__ __launch_bounds__(256) void gn_stats_partial(const float* __restrict__ x) {
    int blk  = blockIdx.x;
    int bg   = blk >> 3;
    int part = blk & 7;
    const float4* p4 = (const float4*)(x + (size_t)bg * CPG * NN + (size_t)part * (CPG * NN / 8));
    const int n4 = (CPG * NN / 8) / 4;
    float s = 0.f, sq = 0.f;
    for (int i = threadIdx.x; i < n4; i += 256) {
        float4 v = p4[i];
        s  += v.x + v.y + v.z + v.w;
        sq += v.x * v.x + v.y * v.y + v.z * v.z + v.w * v.w;
    }
    __shared__ float ss[8], ssq[8];
    for (int o = 16; o; o >>= 1) {
        s  += __shfl_xor_sync(0xffffffffu, s,  o);
        sq += __shfl_xor_sync(0xffffffffu, sq, o);
    }
    if ((threadIdx.x & 31) == 0) { ss[threadIdx.x >> 5] = s; ssq[threadIdx.x >> 5] = sq; }
    __syncthreads();
    if (threadIdx.x == 0) {
        float S = 0.f, SQ = 0.f;
        for (int i = 0; i < 8; i++) { S += ss[i]; SQ += ssq[i]; }
        g_psum[blk] = S;
        g_psq[blk]  = SQ;
    }
}

__global__ void gn_stats_final() {
    int bg = threadIdx.x;
    if (bg >= 16) return;
    float S = 0.f, SQ = 0.f;
    for (int i = 0; i < 8; i++) { S += g_psum[bg * 8 + i]; SQ += g_psq[bg * 8 + i]; }
    const float inv = 1.0f / (float)(CPG * NN);
    float mean = S * inv;
    float var  = SQ * inv - mean * mean;
    g_mean[bg] = mean;
    g_rstd[bg] = rsqrtf(var + EPSV);
}

// ---------------------------------------------------------------------------
// Kernel 2: QKV GEMM (tf32), GN fused on load, pixel permutation folded into
// B staging (R13 base). B-ONLY register prefetch: next k-iter's x loads
// (the long-latency operand) issue after the staging sync and complete under
// this iteration's mma burst. A (W) loads stay in the staging phase (L2-hot).
// ---------------------------------------------------------------------------
__global__ __launch_bounds__(256, 2) void qkv_tc_kernel(
    const float* __restrict__ x, const float* __restrict__ gnw,
    const float* __restrict__ gnb, const float* __restrict__ W,
    const float* __restrict__ bias) {
    __shared__ __align__(16) uint32_t Ap[4][4][272];
    __shared__ __align__(16) uint32_t Bp[4][4][272];
    const int b  = blockIdx.z;
    const int o0 = blockIdx.y * 128;
    const int n0 = blockIdx.x * 128;
    const int tid = threadIdx.x, wid = tid >> 5, lane = tid & 31;
    const int r = lane >> 2, q = lane & 3;
    const int wr = wid >> 2, wc = wid & 3;
    const int which = o0 >> 8;              // 0=q 1=k 2=v (uniform per block)
    const float sc2 = 0.17677669529663687f * LOG2E;

    const int b_cch = tid >> 5, b_nq = (tid & 31) << 2;

    float acc[4][4][4];
#pragma unroll
    for (int mt = 0; mt < 4; mt++)
#pragma unroll
        for (int nt = 0; nt < 4; nt++)
#pragma unroll
            for (int j = 0; j < 4; j++) acc[mt][nt][j] = 0.f;

    // prefetch B for k0 = 0
    float4 xv4[4];
#pragma unroll
    for (int it = 0; it < 4; it++) {
        int cch = b_cch + 8 * it;
        xv4[it] = *(const float4*)&x[((size_t)b * Cc + cch) * NN + n0 + b_nq];
    }

    for (int k0 = 0; k0 < Cc; k0 += 32) {
        __syncthreads();
        // A tile (weights) loaded + staged in-phase (L2-hot)
#pragma unroll
        for (int it = 0; it < 4; it++) {
            int idx = tid + 256 * it;
            int row = idx >> 3, c4 = idx & 7;
            float4 w4 = *(const float4*)&W[(size_t)(o0 + row) * Cc + k0 + c4 * 4];
            float wv[4] = {w4.x, w4.y, w4.z, w4.w};
#pragma unroll
            for (int j = 0; j < 4; j++) {
                int k = c4 * 4 + j, i = k & 7;
                Ap[k >> 3][i & 3][2 * row + (i >> 2)] = f2tf(wv[j]);
            }
        }
        // B tile from prefetched regs: GN + pixel permutation into column order
        const float mu  = g_mean[b * 8 + (k0 >> 5)];
        const float rsd = g_rstd[b * 8 + (k0 >> 5)];
#pragma unroll
        for (int it = 0; it < 4; it++) {
            int cch = b_cch + 8 * it;
            int ch  = k0 + cch;
            float gw = gnw[ch], gb = gnb[ch];
            int pl = cch >> 3, ii = cch & 7;
            int iq = ii & 3, ih = ii >> 2;
            float vv[4] = {xv4[it].x, xv4[it].y, xv4[it].z, xv4[it].w};
#pragma unroll
            for (int j = 0; j < 4; j++) {
                int n = b_nq + j;
                int cpos;
                if (which == 0) {
                    cpos = (n & ~15) | ((n & 7) << 1) | ((n >> 3) & 1);
                } else {
                    int kk = n & 7;
                    cpos = (n & ~7) + ((kk < 4) ? 2 * kk : 2 * kk - 7);
                }
                float gv = (vv[j] - mu) * rsd * gw + gb;
                Bp[pl][iq][2 * cpos + ih] = f2tf(gv);
            }
        }
        __syncthreads();

        // prefetch next B (hidden under the mma burst)
        if (k0 + 32 < Cc) {
#pragma unroll
            for (int it = 0; it < 4; it++) {
                int cch = b_cch + 8 * it;
                xv4[it] = *(const float4*)&x[((size_t)b * Cc + (k0 + 32) + cch) * NN + n0 + b_nq];
            }
        }

#pragma unroll
        for (int kt = 0; kt < 4; kt++) {
            uint32_t af[4][4];
#pragma unroll
            for (int mt = 0; mt < 4; mt++) {
                int m = wr * 64 + mt * 16;
                uint2 lo = *(const uint2*)&Ap[kt][q][2 * (m + r)];
                uint2 hi = *(const uint2*)&Ap[kt][q][2 * (m + 8 + r)];
                af[mt][0] = lo.x; af[mt][1] = hi.x; af[mt][2] = lo.y; af[mt][3] = hi.y;
            }
            uint2 bfv[4];
#pragma unroll
            for (int nt = 0; nt < 4; nt++)
                bfv[nt] = *(const uint2*)&Bp[kt][q][2 * (wc * 32 + nt * 8 + r)];
#pragma unroll
            for (int mt = 0; mt < 4; mt++)
#pragma unroll
                for (int nt = 0; nt < 4; nt++) {
                    uint32_t bb[2] = {bfv[nt].x, bfv[nt].y};
                    mma_tf32(acc[mt][nt], af[mt], bb, acc[mt][nt]);
                }
        }
    }

    // ---- epilogue: affine addresses (permutation already in column order) --
    const size_t bb0 = (size_t)b * NH;
    if (which == 0) {
#pragma unroll
        for (int mt = 0; mt < 4; mt++)
#pragma unroll
            for (int hf_i = 0; hf_i < 2; hf_i++) {
                int row = o0 + wr * 64 + mt * 16 + r + 8 * hf_i;
                float bi = bias[row];
                int h = (row >> 5) & 7, d = row & 31;
                int kt2 = d >> 3, qq2 = d & 3, hf = (d >> 2) & 1;
                uint32_t* qb = g_q2 + ((bb0 + h) * 256 + (n0 >> 4)) * 512
                               + kt2 * 128 + qq2 * 4 + 2 * hf;
#pragma unroll
                for (int nt = 0; nt < 4; nt++) {
                    int c = wc * 32 + nt * 8 + 2 * q;
                    uint2 v;
                    v.x = f2tf((acc[mt][nt][hf_i * 2 + 0] + bi) * sc2);
                    v.y = f2tf((acc[mt][nt][hf_i * 2 + 1] + bi) * sc2);
                    *(uint2*)&qb[(c >> 4) * 512 + ((c >> 1) & 7) * 16] = v;
                }
            }
    } else if (which == 1) {
#pragma unroll
        for (int mt = 0; mt < 4; mt++)
#pragma unroll
            for (int hf_i = 0; hf_i < 2; hf_i++) {
                int row = o0 + wr * 64 + mt * 16 + r + 8 * hf_i;
                float bi = bias[row];
                int h = (row >> 5) & 7, d = row & 31;
                int plane = (d >> 3) * 4 + (d & 3), hf = (d >> 2) & 1;
                uint32_t* kb = g_k2 + (bb0 + h) * 64 * KT_BLK
                               + (size_t)(n0 >> 6) * KT_BLK + plane * KT_ROW + hf;
#pragma unroll
                for (int nt = 0; nt < 4; nt++)
#pragma unroll
                    for (int jj = 0; jj < 2; jj++) {
                        int c = wc * 32 + nt * 8 + 2 * q + jj;
                        kb[(c >> 6) * KT_BLK + 2 * (c & 63)] =
                            f2tf(acc[mt][nt][hf_i * 2 + jj] + bi);
                    }
            }
    } else {
#pragma unroll
        for (int mt = 0; mt < 4; mt++)
#pragma unroll
            for (int hf_i = 0; hf_i < 2; hf_i++) {
                int row = o0 + wr * 64 + mt * 16 + r + 8 * hf_i;
                float bi = bias[row];
                int h = (row >> 5) & 7, d = row & 31;
                uint32_t* vb = g_v2 + (bb0 + h) * 64 * VT_BLK
                               + (size_t)(n0 >> 6) * VT_BLK + 2 * d;
#pragma unroll
                for (int nt = 0; nt < 4; nt++) {
                    int c = wc * 32 + nt * 8 + 2 * q;
                    int plane = ((c & 63) >> 3) * 4 + q;
                    uint2 v;
                    v.x = f2tf(acc[mt][nt][hf_i * 2 + 0] + bi);
                    v.y = f2tf(acc[mt][nt][hf_i * 2 + 1] + bi);
                    *(uint2*)&vb[(c >> 6) * VT_BLK + plane * VT_ROW] = v;
                }
            }
    }
}

// ---------------------------------------------------------------------------
// Kernel 3: flash attention (round-11 best config, unchanged).
// ---------------------------------------------------------------------------
__global__ __launch_bounds__(256, 2) void attn_tc_kernel() {
    __shared__ __align__(16) uint32_t Ks[2][KT_BLK];
    __shared__ __align__(16) uint32_t Vs[2][VT_BLK];

    const int b  = blockIdx.z;
    const int h  = blockIdx.y;
    const int q0 = blockIdx.x * 256;
    const int tid = threadIdx.x, wid = tid >> 5, lane = tid & 31;
    const int r = lane >> 2, q = lane & 3;
    const size_t bh = (size_t)b * NH + h;

    uint32_t qa[2][4][4];
#pragma unroll
    for (int mt = 0; mt < 2; mt++) {
        const int chunk = (q0 >> 4) + wid * 2 + mt;
#pragma unroll
        for (int kt = 0; kt < 4; kt++) {
            uint4 v4 = *(const uint4*)&g_q2[(((bh * 256 + chunk) * 4 + kt) * 32 + lane) * 4];
            qa[mt][kt][0] = v4.x; qa[mt][kt][1] = v4.y;
            qa[mt][kt][2] = v4.z; qa[mt][kt][3] = v4.w;
        }
    }

    float o0a[4][4], o1a[4][4];
#pragma unroll
    for (int i = 0; i < 4; i++)
#pragma unroll
        for (int j = 0; j < 4; j++) { o0a[i][j] = 0.f; o1a[i][j] = 0.f; }
    float lsum[2][2] = {{0.f, 0.f}, {0.f, 0.f}};

    const char* kgm = (const char*)(g_k2 + bh * 64 * KT_BLK);
    const char* vgm = (const char*)(g_v2 + bh * 64 * VT_BLK);
    uint32_t ks_s[2], vs_s[2];
    ks_s[0] = (uint32_t)__cvta_generic_to_shared(&Ks[0][0]);
    ks_s[1] = (uint32_t)__cvta_generic_to_shared(&Ks[1][0]);
    vs_s[0] = (uint32_t)__cvta_generic_to_shared(&Vs[0][0]);
    vs_s[1] = (uint32_t)__cvta_generic_to_shared(&Vs[1][0]);

    {
        for (int off = tid * 16; off < TILE_BYTES; off += 4096) {
            if (off < KT_BYTES) CP16(ks_s[0] + off, kgm + off);
            else                CP16(vs_s[0] + (off - KT_BYTES), vgm + (off - KT_BYTES));
        }
        CP_COMMIT();
    }

#pragma unroll 1
    for (int t = 0; t < NN / 64; t++) {
        const int cur = t & 1;
        const bool more = (t + 1 < NN / 64);
        if (more) {
            const char* ksrc = kgm + (size_t)(t + 1) * KT_BYTES;
            const char* vsrc = vgm + (size_t)(t + 1) * VT_BYTES;
            const int nxt = 1 - cur;
            for (int off = tid * 16; off < TILE_BYTES; off += 4096) {
                if (off < KT_BYTES) CP16(ks_s[nxt] + off, ksrc + off);
                else                CP16(vs_s[nxt] + (off - KT_BYTES), vsrc + (off - KT_BYTES));
            }
            CP_COMMIT();
            asm volatile("cp.async.wait_group 1;");
        } else {
            asm volatile("cp.async.wait_group 0;");
        }
        __syncthreads();

        const uint32_t* Kc = Ks[cur];
        const uint32_t* Vc = Vs[cur];

        float s0[8][4], s1[8][4];
        float rs00 = 0.f, rs01 = 0.f, rs10 = 0.f, rs11 = 0.f;

#pragma unroll
        for (int nt = 0; nt < 8; nt++) {
            uint2 bfk[4];
#pragma unroll
            for (int kt = 0; kt < 4; kt++)
                bfk[kt] = *(const uint2*)&Kc[(kt * 4 + q) * KT_ROW + 2 * (nt * 8 + r)];
#pragma unroll
            for (int j = 0; j < 4; j++) { s0[nt][j] = 0.f; s1[nt][j] = 0.f; }
#pragma unroll
            for (int kt = 0; kt < 4; kt++) {
                uint32_t bb[2] = {bfk[kt].x, bfk[kt].y};
                mma_tf32(s0[nt], qa[0][kt], bb, s0[nt]);
                mma_tf32(s1[nt], qa[1][kt], bb, s1[nt]);
            }
            if (nt > 0) {
                const int p = nt - 1;
                s0[p][0] = ex2f(s0[p][0]); rs00 += s0[p][0];
                s0[p][1] = ex2f(s0[p][1]); rs00 += s0[p][1];
                s0[p][2] = ex2f(s0[p][2]); rs01 += s0[p][2];
                s0[p][3] = ex2f(s0[p][3]); rs01 += s0[p][3];
            }
        }
        s0[7][0] = ex2f(s0[7][0]); rs00 += s0[7][0];
        s0[7][1] = ex2f(s0[7][1]); rs00 += s0[7][1];
        s0[7][2] = ex2f(s0[7][2]); rs01 += s0[7][2];
        s0[7][3] = ex2f(s0[7][3]); rs01 += s0[7][3];

        s1[0][0] = ex2f(s1[0][0]); rs10 += s1[0][0];
        s1[0][1] = ex2f(s1[0][1]); rs10 += s1[0][1];
        s1[0][2] = ex2f(s1[0][2]); rs11 += s1[0][2];
        s1[0][3] = ex2f(s1[0][3]); rs11 += s1[0][3];

#pragma unroll
        for (int grp = 0; grp < 8; grp++) {
            if (grp < 7) {
                const int p = grp + 1;
                s1[p][0] = ex2f(s1[p][0]); rs10 += s1[p][0];
                s1[p][1] = ex2f(s1[p][1]); rs10 += s1[p][1];
                s1[p][2] = ex2f(s1[p][2]); rs11 += s1[p][2];
                s1[p][3] = ex2f(s1[p][3]); rs11 += s1[p][3];
            }
            const uint32_t* vr2 = Vc + (grp * 4 + q) * VT_ROW;
            uint32_t pa0[4], pa1[4];
            pa0[0] = __float_as_uint(s0[grp][0]);
            pa0[1] = __float_as_uint(s0[grp][2]);
            pa0[2] = __float_as_uint(s0[grp][1]);
            pa0[3] = __float_as_uint(s0[grp][3]);
            pa1[0] = __float_as_uint(s1[grp][0]);
            pa1[1] = __float_as_uint(s1[grp][2]);
            pa1[2] = __float_as_uint(s1[grp][1]);
            pa1[3] = __float_as_uint(s1[grp][3]);
#pragma unroll
            for (int nt = 0; nt < 4; nt++) {
                uint2 bf = *(const uint2*)&vr2[2 * (nt * 8 + r)];
                uint32_t bb[2] = {bf.x, bf.y};
                mma_tf32(o0a[nt], pa0, bb, o0a[nt]);
                mma_tf32(o1a[nt], pa1, bb, o1a[nt]);
            }
        }
        lsum[0][0] += rs00; lsum[0][1] += rs01;
        lsum[1][0] += rs10; lsum[1][1] += rs11;
        __syncthreads();
    }

#pragma unroll
    for (int mt = 0; mt < 2; mt++) {
        float rs0 = lsum[mt][0], rs1 = lsum[mt][1];
        rs0 += __shfl_xor_sync(0xffffffffu, rs0, 1);
        rs0 += __shfl_xor_sync(0xffffffffu, rs0, 2);
        rs1 += __shfl_xor_sync(0xffffffffu, rs1, 1);
        rs1 += __shfl_xor_sync(0xffffffffu, rs1, 2);
        float inv0 = 1.0f / rs0, inv1 = 1.0f / rs1;
        const int gr0 = q0 + wid * 32 + mt * 16 + r;
        const int gr1 = gr0 + 8;
        float (*oo)[4] = (mt == 0) ? o0a : o1a;
#pragma unroll
        for (int nt = 0; nt < 4; nt++) {
            int d = nt * 8 + 2 * q;
            float* base = g_o + (bh * HD + d) * NN;
            base[gr0]      = oo[nt][0] * inv0;
            base[NN + gr0] = oo[nt][1] * inv0;
            base[gr1]      = oo[nt][2] * inv1;
            base[NN + gr1] = oo[nt][3] * inv1;
        }
    }
}

// ---------------------------------------------------------------------------
// Kernel 4: output projection GEMM (tf32), B-only register prefetch.
// ---------------------------------------------------------------------------
__global__ __launch_bounds__(256, 2) void proj_tc_kernel(
    const float* __restrict__ W, const float* __restrict__ bias,
    float* __restrict__ out) {
    __shared__ __align__(16) uint32_t Ap[4][4][272];
    __shared__ __align__(16) uint32_t Bp[4][4][272];
    const int b  = blockIdx.z;
    const int o0 = blockIdx.y * 128;
    const int n0 = blockIdx.x * 128;
    const int tid = threadIdx.x, wid = tid >> 5, lane = tid & 31;
    const int r = lane >> 2, q = lane & 3;
    const int wr = wid >> 2, wc = wid & 3;

    const int b_cch = tid >> 5, b_nq = (tid & 31) << 2;

    float acc[4][4][4];
#pragma unroll
    for (int mt = 0; mt < 4; mt++)
#pragma unroll
        for (int nt = 0; nt < 4; nt++)
#pragma unroll
            for (int j = 0; j < 4; j++) acc[mt][nt][j] = 0.f;

    float4 xv4[4];
#pragma unroll
    for (int it = 0; it < 4; it++) {
        int cch = b_cch + 8 * it;
        xv4[it] = *(const float4*)&g_o[((size_t)b * Cc + cch) * NN + n0 + b_nq];
    }

    for (int k0 = 0; k0 < Cc; k0 += 32) {
        __syncthreads();
#pragma unroll
        for (int it = 0; it < 4; it++) {
            int idx = tid + 256 * it;
            int row = idx >> 3, c4 = idx & 7;
            float4 w4 = *(const float4*)&W[(size_t)(o0 + row) * Cc + k0 + c4 * 4];
            float wv[4] = {w4.x, w4.y, w4.z, w4.w};
#pragma unroll
            for (int j = 0; j < 4; j++) {
                int k = c4 * 4 + j, i = k & 7;
                Ap[k >> 3][i & 3][2 * row + (i >> 2)] = f2tf(wv[j]);
            }
        }
#pragma unroll
        for (int it = 0; it < 4; it++) {
            int cch = b_cch + 8 * it;
            int pl = cch >> 3, ii = cch & 7;
            int iq = ii & 3, ih = ii >> 2;
            float vv[4] = {xv4[it].x, xv4[it].y, xv4[it].z, xv4[it].w};
#pragma unroll
            for (int j = 0; j < 4; j++)
                Bp[pl][iq][2 * (b_nq + j) + ih] = f2tf(vv[j]);
        }
        __syncthreads();

        if (k0 + 32 < Cc) {
#pragma unroll
            for (int it = 0; it < 4; it++) {
                int cch = b_cch + 8 * it;
                xv4[it] = *(const float4*)&g_o[((size_t)b * Cc + (k0 + 32) + cch) * NN + n0 + b_nq];
            }
        }

#pragma unroll
        for (int kt = 0; kt < 4; kt++) {
            uint32_t af[4][4];
#pragma unroll
            for (int mt = 0; mt < 4; mt++) {
                int m = wr * 64 + mt * 16;
                uint2 lo = *(const uint2*)&Ap[kt][q][2 * (m + r)];
                uint2 hi = *(const uint2*)&Ap[kt][q][2 * (m + 8 + r)];
                af[mt][0] = lo.x; af[mt][1] = hi.x; af[mt][2] = lo.y; af[mt][3] = hi.y;
            }
            uint2 bfv[4];
#pragma unroll
            for (int nt = 0; nt < 4; nt++)
                bfv[nt] = *(const uint2*)&Bp[kt][q][2 * (wc * 32 + nt * 8 + r)];
#pragma unroll
            for (int mt = 0; mt < 4; mt++)
#pragma unroll
                for (int nt = 0; nt < 4; nt++) {
                    uint32_t bb[2] = {bfv[nt].x, bfv[nt].y};
                    mma_tf32(acc[mt][nt], af[mt], bb, acc[mt][nt]);
                }
        }
    }

#pragma unroll
    for (int mt = 0; mt < 4; mt++) {
        int row0 = o0 + wr * 64 + mt * 16 + r;
        int row1 = row0 + 8;
        float bi0 = bias[row0], bi1 = bias[row1];
        float* p0 = out + ((size_t)b * Cc + row0) * NN;
        float* p1 = out + ((size_t)b * Cc + row1) * NN;
#pragma unroll
        for (int nt = 0; nt < 4; nt++) {
            int n = n0 + wc * 32 + nt * 8 + 2 * q;
            float2 v0 = make_float2(acc[mt][nt][0] + bi0, acc[mt][nt][1] + bi0);
            float2 v1 = make_float2(acc[mt][nt][2] + bi1, acc[mt][nt][3] + bi1);
            *(float2*)&p0[n] = v0;
            *(float2*)&p1[n] = v1;
        }
    }
}

// ---------------------------------------------------------------------------
// Launch
// ---------------------------------------------------------------------------
extern "C" void kernel_launch(void* const* d_in, const int* in_sizes, int n_in,
                              void* d_out, int out_size) {
    const float* x    = (const float*)d_in[0];
    const float* gnw  = (const float*)d_in[1];
    const float* gnb  = (const float*)d_in[2];
    const float* wqkv = (const float*)d_in[3];
    const float* bqkv = (const float*)d_in[4];
    const float* wproj= (const float*)d_in[5];
    const float* bproj= (const float*)d_in[6];
    float* out = (float*)d_out;

    gn_stats_partial<<<128, 256>>>(x);
    gn_stats_final<<<1, 16>>>();

    dim3 gq(NN / 128, (3 * Cc) / 128, Bz);
    qkv_tc_kernel<<<gq, 256>>>(x, gnw, gnb, wqkv, bqkv);

    dim3 ga(NN / 256, NH, Bz);
    attn_tc_kernel<<<ga, 256>>>();

    dim3 gp(NN / 128, Cc / 128, Bz);
    proj_tc_kernel<<<gp, 256>>>(wproj, bproj, out);
}